// round 2
// baseline (speedup 1.0000x reference)
#include <cuda_runtime.h>

// BG_LSTM: B=512 batch, T=512 steps, H=256 hidden, input size 1.
// Design: 16 clusters x 8 CTAs. Cluster c owns batch tile [32c, 32c+32).
// CTA rank r in cluster owns hidden units [32r, 32r+32) (all 4 gates) and
// keeps its W_hh slice (128 rows x 256 k, fp32, k-major) resident in SMEM
// for the whole kernel. Cell state c lives in registers. h is exchanged
// between the 8 CTAs of a cluster through a double-buffered global array,
// with one barrier.cluster per timestep. Inner product uses fma.rn.f32x2
// (2 fp32 MACs/instr) pairing batches in 64-bit registers.

#define BB 512
#define TT 512
#define HH 256
#define CLUSTER 8
#define NCTA 128
#define UPC 32          // hidden units per CTA
#define BPT 32          // batch tile per cluster
#define NTHREADS 256
#define HS_STRIDE 36    // padded shared h stride (floats; 144 B, 16B-aligned)

// h exchange buffers: [buf][unit][batch], transposed so the compute-side
// store is a single float4 per thread and fc head reads coalesced.
__device__ float g_h[2][HH][BB];

typedef unsigned long long u64;

__device__ __forceinline__ u64 splat2(float w) {
    u64 r; unsigned int wu = __float_as_uint(w);
    asm("mov.b64 %0, {%1, %1};" : "=l"(r) : "r"(wu));
    return r;
}
__device__ __forceinline__ u64 pack2(float a, float b) {
    u64 r;
    asm("mov.b64 %0, {%1, %2};" : "=l"(r)
        : "r"(__float_as_uint(a)), "r"(__float_as_uint(b)));
    return r;
}
__device__ __forceinline__ void unpack2(u64 v, float &a, float &b) {
    unsigned int lo, hi;
    asm("mov.b64 {%0, %1}, %2;" : "=r"(lo), "=r"(hi) : "l"(v));
    a = __uint_as_float(lo); b = __uint_as_float(hi);
}
__device__ __forceinline__ void ffma2(u64 &acc, u64 a, u64 b) {
    asm("fma.rn.f32x2 %0, %1, %2, %3;" : "=l"(acc) : "l"(a), "l"(b), "l"(acc));
}
__device__ __forceinline__ void cluster_sync_all() {
    asm volatile("barrier.cluster.arrive.aligned;" ::: "memory");
    asm volatile("barrier.cluster.wait.aligned;" ::: "memory");
}
__device__ __forceinline__ float sigm(float x) {
    return __fdividef(1.0f, 1.0f + __expf(-x));
}
__device__ __forceinline__ float tanhe(float x) {
    return __fdividef(2.0f, 1.0f + __expf(-2.0f * x)) - 1.0f;
}

extern __shared__ __align__(16) float smem[];  // Ws[32768] ++ hs[256*36]

__global__ void __cluster_dims__(CLUSTER, 1, 1) __launch_bounds__(NTHREADS, 1)
lstm_kernel(const float* __restrict__ x,    const float* __restrict__ wih,
            const float* __restrict__ whh,  const float* __restrict__ bih,
            const float* __restrict__ bhh,  const float* __restrict__ wfc,
            const float* __restrict__ bfc,  float* __restrict__ out)
{
    float* Ws = smem;                 // [k][u_local*4+g], 256*128 floats
    float* hs = smem + UPC * 4 * HH;  // [unit][batch_local], stride 36

    const int t      = threadIdx.x;
    const int cta    = blockIdx.x;
    const int rank   = cta & (CLUSTER - 1);
    const int cl     = cta / CLUSTER;
    const int batch0 = cl * BPT;
    const int unit0  = rank * UPC;
    const int u      = t >> 3;   // 0..31: my hidden unit (local)
    const int bg     = t & 7;    // 0..7 : my 4-batch group

    // ---- Stage W_hh slice into SMEM, k-major: Ws[k*128 + u_l*4+g] ----
    {
        const float4* w4 = (const float4*)whh;
        #pragma unroll
        for (int j = 0; j < 32; j++) {
            int idx   = t + j * NTHREADS;   // 0..8191 (float4 granules)
            int row_l = idx >> 6;           // 0..127
            int k4    = idx & 63;
            int u_l   = row_l >> 2, g = row_l & 3;
            float4 w  = __ldg(&w4[(g * HH + unit0 + u_l) * (HH / 4) + k4]);
            Ws[(k4 * 4 + 0) * 128 + row_l] = w.x;
            Ws[(k4 * 4 + 1) * 128 + row_l] = w.y;
            Ws[(k4 * 4 + 2) * 128 + row_l] = w.z;
            Ws[(k4 * 4 + 3) * 128 + row_l] = w.w;
        }
    }

    // ---- Per-thread gate params (unit u, gates i,f,g,o) ----
    float wih_r[4], bias_r[4];
    #pragma unroll
    for (int g = 0; g < 4; g++) {
        int r = g * HH + unit0 + u;
        wih_r[g]  = __ldg(&wih[r]);
        bias_r[g] = __ldg(&bih[r]) + __ldg(&bhh[r]);
    }

    // ---- Zero my slice of g_h[0] (initial h = 0) ----
    {
        float4 z = make_float4(0.f, 0.f, 0.f, 0.f);
        __stcg((float4*)&g_h[0][unit0 + u][batch0 + bg * 4], z);
    }
    float c0 = 0.f, c1 = 0.f, c2 = 0.f, c3 = 0.f;

    __syncthreads();
    __threadfence();
    cluster_sync_all();

    const float* xb = x + (batch0 + bg * 4) * TT;  // my 4 batches' x rows
    int p = 0;

    for (int step = 0; step < TT; step++) {
        // x for my 4 batches (few distinct addresses per warp, L2-resident)
        float xv0 = __ldg(&xb[0 * TT + step]);
        float xv1 = __ldg(&xb[1 * TT + step]);
        float xv2 = __ldg(&xb[2 * TT + step]);
        float xv3 = __ldg(&xb[3 * TT + step]);

        // Load the full h tile [256 units][32 batches] into shared
        #pragma unroll
        for (int j = 0; j < 8; j++) {
            int row = (t >> 3) + j * 32;
            float4 v = __ldcg((const float4*)&g_h[p][row][batch0 + (t & 7) * 4]);
            *(float4*)&hs[row * HS_STRIDE + (t & 7) * 4] = v;
        }
        __syncthreads();

        // Accumulators: 4 gates x 2 batch-pairs (f32x2)
        u64 acc[4][2];
        #pragma unroll
        for (int g = 0; g < 4; g++) {
            acc[g][0] = pack2(fmaf(xv0, wih_r[g], bias_r[g]),
                              fmaf(xv1, wih_r[g], bias_r[g]));
            acc[g][1] = pack2(fmaf(xv2, wih_r[g], bias_r[g]),
                              fmaf(xv3, wih_r[g], bias_r[g]));
        }

        const float* wp = Ws + u * 4;
        const float* hp = hs + bg * 4;
        #pragma unroll 4
        for (int k = 0; k < HH; k++) {
            float4 w = *(const float4*)wp;  wp += 128;
            u64 h01  = *(const u64*)hp;
            u64 h23  = *(const u64*)(hp + 2);
            hp += HS_STRIDE;
            u64 wi = splat2(w.x), wf = splat2(w.y);
            u64 wg = splat2(w.z), wo = splat2(w.w);
            ffma2(acc[0][0], wi, h01);  ffma2(acc[0][1], wi, h23);
            ffma2(acc[1][0], wf, h01);  ffma2(acc[1][1], wf, h23);
            ffma2(acc[2][0], wg, h01);  ffma2(acc[2][1], wg, h23);
            ffma2(acc[3][0], wo, h01);  ffma2(acc[3][1], wo, h23);
        }

        float gi[4], gf[4], gg[4], go[4];
        unpack2(acc[0][0], gi[0], gi[1]);  unpack2(acc[0][1], gi[2], gi[3]);
        unpack2(acc[1][0], gf[0], gf[1]);  unpack2(acc[1][1], gf[2], gf[3]);
        unpack2(acc[2][0], gg[0], gg[1]);  unpack2(acc[2][1], gg[2], gg[3]);
        unpack2(acc[3][0], go[0], go[1]);  unpack2(acc[3][1], go[2], go[3]);

        float cc[4] = {c0, c1, c2, c3};
        float hv[4];
        #pragma unroll
        for (int b = 0; b < 4; b++) {
            float iv = sigm(gi[b]);
            float fv = sigm(gf[b]);
            float gv = tanhe(gg[b]);
            float ov = sigm(go[b]);
            cc[b] = fv * cc[b] + iv * gv;
            hv[b] = ov * tanhe(cc[b]);
        }
        c0 = cc[0]; c1 = cc[1]; c2 = cc[2]; c3 = cc[3];

        float4 ho = make_float4(hv[0], hv[1], hv[2], hv[3]);
        __stcg((float4*)&g_h[p ^ 1][unit0 + u][batch0 + bg * 4], ho);

        __threadfence();
        cluster_sync_all();   // also serves as the intra-CTA barrier
        p ^= 1;
    }

    // ---- FC head: out[b] = sum_u relu(h[b,u]) * wfc[u] + bfc ----
    if (rank == 0) {
        int b_l = t & 31, seg = t >> 5;  // 8 segments of 32 units
        float s = 0.f;
        #pragma unroll
        for (int j = 0; j < 32; j++) {
            int uu = seg * 32 + j;
            float hval = __ldcg(&g_h[p][uu][batch0 + b_l]);
            s = fmaf(fmaxf(hval, 0.f), __ldg(&wfc[uu]), s);
        }
        float* red = smem;  // Ws region no longer needed
        __syncthreads();
        red[seg * 32 + b_l] = s;
        __syncthreads();
        if (t < 32) {
            float tot = __ldg(bfc);
            #pragma unroll
            for (int sg = 0; sg < 8; sg++) tot += red[sg * 32 + t];
            out[batch0 + t] = tot;
        }
    }
}

extern "C" void kernel_launch(void* const* d_in, const int* in_sizes, int n_in,
                              void* d_out, int out_size) {
    const float* x   = (const float*)d_in[0];
    const float* wih = (const float*)d_in[1];
    const float* whh = (const float*)d_in[2];
    const float* bih = (const float*)d_in[3];
    const float* bhh = (const float*)d_in[4];
    const float* wfc = (const float*)d_in[5];
    const float* bfc = (const float*)d_in[6];
    (void)in_sizes; (void)n_in; (void)out_size;

    size_t shmem = (size_t)(UPC * 4 * HH + HH * HS_STRIDE) * sizeof(float); // 167936 B
    cudaFuncSetAttribute(lstm_kernel,
                         cudaFuncAttributeMaxDynamicSharedMemorySize, (int)shmem);
    lstm_kernel<<<NCTA, NTHREADS, shmem>>>(x, wih, whh, bih, bhh, wfc, bfc,
                                           (float*)d_out);
}